// round 14
// baseline (speedup 1.0000x reference)
#include <cuda_runtime.h>
#include <cuda_fp16.h>
#include <cstdint>
#include <cstddef>

// ---------------- problem constants ----------------
#define Bb 32
#define Ss 2048
#define Ee 1024
#define Dd 1024
#define Mm (Ss * Bb)          // 65536 GEMM rows

// ---------------- main GEMM tiling -----------------
#define BM 128
#define BN 256
#define BK 64                 // fp16 elements per K-chunk (4 k16-steps)
#define NCH (Ee / BK)         // 16
#define STAGE 49152           // A 16K | B 32K
#define B_OFF 16384
#define NSTG 3
#define DECOFF (NSTG * STAGE) // 147456
#define SMEMSZ (DECOFF + Bb * BN * 4)   // +32KB dec tile = 180224
#define NTHR 512              // 16 warps: 2m x 8n, warp tile 64x32

// ---------------- scratch (__device__ globals; no allocs allowed) ----------
__device__ float g_scores[Bb * Ss];                       // 256 KB
__device__ float g_dec[Bb * Dd];                          // 128 KB
__device__ __half g_ench[(size_t)Mm * Ee];                // 128 MB
__device__ __half g_weh[Dd * Ee];                         // 2 MB

// ---------------- helpers (sm_80-universal PTX only) ----------------
__device__ __forceinline__ uint32_t smem_u32(const void* p) {
    uint32_t a;
    asm("{ .reg .u64 t; cvta.to.shared.u64 t, %1; cvt.u32.u64 %0, t; }" : "=r"(a) : "l"(p));
    return a;
}
__device__ __forceinline__ float fast_tanh(float x) {
    float e = __expf(2.0f * x);
    return 1.0f - __fdividef(2.0f, e + 1.0f);
}
#define CPA16(dst, src) asm volatile("cp.async.cg.shared.global [%0], [%1], 16;" :: "r"(dst), "l"(src) : "memory")
#define CPA_COMMIT()    asm volatile("cp.async.commit_group;" ::: "memory")
#define CPA_WAIT1()     asm volatile("cp.async.wait_group 1;" ::: "memory")

#define LDSM4(r, a)                                                              \
    asm volatile("ldmatrix.sync.aligned.m8n8.x4.shared.b16 {%0,%1,%2,%3}, [%4];" \
        : "=r"((r)[0]), "=r"((r)[1]), "=r"((r)[2]), "=r"((r)[3]) : "r"(a))

#define MMA_F16(d, a, b0, b1)                                                    \
    asm volatile("mma.sync.aligned.m16n8k16.row.col.f32.f16.f16.f32 "            \
        "{%0,%1,%2,%3}, {%4,%5,%6,%7}, {%8,%9}, {%0,%1,%2,%3};"                  \
        : "+f"((d)[0]), "+f"((d)[1]), "+f"((d)[2]), "+f"((d)[3])                 \
        : "r"((a)[0]), "r"((a)[1]), "r"((a)[2]), "r"((a)[3]),                    \
          "r"(b0), "r"(b1))

// ---------------------------------------------------------------------------
// K-split-enc: f32 -> fp16; ALSO zeroes g_scores (blocks 0..255) — stream
// order guarantees zeros are visible before k_main's atomics.
// ---------------------------------------------------------------------------
__global__ void k_split_enc(const float4* __restrict__ src) {
    if (blockIdx.x < 256) g_scores[blockIdx.x * 256 + threadIdx.x] = 0.0f;
    const size_t n8 = (size_t)Mm * Ee / 8;
    size_t i = (size_t)blockIdx.x * blockDim.x + threadIdx.x;
    const size_t stride = (size_t)gridDim.x * blockDim.x;
    uint4* hi = (uint4*)g_ench;
    for (; i < n8; i += stride) {
        float4 x0 = src[2 * i], x1 = src[2 * i + 1];
        float xs[8] = {x0.x, x0.y, x0.z, x0.w, x1.x, x1.y, x1.z, x1.w};
        uint32_t h[4];
#pragma unroll
        for (int j = 0; j < 4; ++j) {
            __half h0 = __float2half_rn(xs[2 * j]);
            __half h1 = __float2half_rn(xs[2 * j + 1]);
            h[j] = (uint32_t)__half_as_ushort(h0) | ((uint32_t)__half_as_ushort(h1) << 16);
        }
        hi[i] = make_uint4(h[0], h[1], h[2], h[3]);
    }
}

// ---------------------------------------------------------------------------
// K-split-we: f32 -> fp16
// ---------------------------------------------------------------------------
__global__ void k_split_we(const float4* __restrict__ src) {
    const size_t n8 = (size_t)Dd * Ee / 8;
    size_t i = (size_t)blockIdx.x * blockDim.x + threadIdx.x;
    const size_t stride = (size_t)gridDim.x * blockDim.x;
    uint4* hi = (uint4*)g_weh;
    for (; i < n8; i += stride) {
        float4 x0 = src[2 * i], x1 = src[2 * i + 1];
        float xs[8] = {x0.x, x0.y, x0.z, x0.w, x1.x, x1.y, x1.z, x1.w};
        uint32_t h[4];
#pragma unroll
        for (int j = 0; j < 4; ++j) {
            __half h0 = __float2half_rn(xs[2 * j]);
            __half h1 = __float2half_rn(xs[2 * j + 1]);
            h[j] = (uint32_t)__half_as_ushort(h0) | ((uint32_t)__half_as_ushort(h1) << 16);
        }
        hi[i] = make_uint4(h[0], h[1], h[2], h[3]);
    }
}

// ---------------------------------------------------------------------------
// K1: dec_proj[b,d] = hidden[b,:] . Wd[d,:]
// ---------------------------------------------------------------------------
__global__ void k_dec(const float* __restrict__ hidden, const float* __restrict__ Wd) {
    __shared__ __align__(16) float hs[Bb][132];
    __shared__ __align__(16) float ws[8][132];
    const int tid = threadIdx.x;
    const int b = tid & 31;
    const int dg = tid >> 5;
    const int d = blockIdx.x * 8 + dg;
    float acc = 0.0f;
    for (int kc = 0; kc < Dd; kc += 128) {
#pragma unroll
        for (int i = 0; i < 4; ++i) {           // hidden chunk: 1024 float4
            const int idx = tid + 256 * i;
            const int r = idx >> 5, c = idx & 31;
            *(float4*)&hs[r][c * 4] = *(const float4*)&hidden[r * Dd + kc + c * 4];
        }
        {                                        // Wd chunk: 256 float4
            const int r = tid >> 5, c = tid & 31;
            *(float4*)&ws[r][c * 4] = *(const float4*)&Wd[(size_t)(blockIdx.x * 8 + r) * Dd + kc + c * 4];
        }
        __syncthreads();
        float a0 = 0.f, a1 = 0.f;
#pragma unroll
        for (int j = 0; j < 32; j += 2) {
            float4 h4 = *(const float4*)&hs[b][j * 4];
            float4 w4 = *(const float4*)&ws[dg][j * 4];
            a0 += h4.x * w4.x + h4.y * w4.y + h4.z * w4.z + h4.w * w4.w;
            float4 h5 = *(const float4*)&hs[b][j * 4 + 4];
            float4 w5 = *(const float4*)&ws[dg][j * 4 + 4];
            a1 += h5.x * w5.x + h5.y * w5.y + h5.z * w5.z + h5.w * w5.w;
        }
        acc += a0 + a1;
        __syncthreads();
    }
    g_dec[b * Dd + d] = acc;
}

// ---------------------------------------------------------------------------
// K2: single-pass fp16 warp-MMA GEMM + fused tanh/v epilogue
//   BK=64 (4 k16-steps/chunk): per-chunk fixed costs (wait/sync/loader)
//   halved vs BK=32. 16 warps (2m x 8n). 3-stage cp.async, one sync/chunk:
//     wait(c) -> sync -> load(c+2) -> compute(c)
//   Safe: barrier at iter c proves all warps finished compute(c-1), whose
//   buffer (c+2)%3 is the one being overwritten.
// ---------------------------------------------------------------------------
__global__ void __launch_bounds__(NTHR, 1)
k_main(const float* __restrict__ v) {
    extern __shared__ __align__(16) char smem[];
    const uint32_t sb = smem_u32(smem);
    const int tid = threadIdx.x;
    const int lane = tid & 31;
    const int wid = tid >> 5;
    const int wm = wid & 1;              // m half (64 rows)
    const int wn = wid >> 1;             // n eighth (32 cols)
    const int mBase = blockIdx.y * BM;
    const int nBase = blockIdx.x * BN;

    // ---- stage dec tile [32b x 256n] into smem (read only in epilogue)
    {
        float4* dv = (float4*)(smem + DECOFF);
#pragma unroll
        for (int i = 0; i < 4; ++i) {
            const int idx = tid + NTHR * i;             // 2048 float4
            const int b = idx >> 6, nq = idx & 63;
            dv[idx] = *(const float4*)(g_dec + b * Dd + nBase + nq * 4);
        }
    }

    // ---- per-lane ldmatrix offsets (relative to stage base, ks=0)
    const int a_r = (lane & 7) + ((lane >> 3) & 1) * 8;   // row within m16
    const int a_h = lane >> 4;                            // k-half (16B unit)
    uint32_t aoff[4];
#pragma unroll
    for (int mf = 0; mf < 4; ++mf) {
        const int m = wm * 64 + mf * 16 + a_r;
        aoff[mf] = m * 32 + ((a_h ^ ((m >> 2) & 1)) << 4);
    }
    const int bx_r = (lane & 7) + ((lane >> 4) & 1) * 8;
    const int bx_h = (lane >> 3) & 1;
    uint32_t boff[2];
#pragma unroll
    for (int nq = 0; nq < 2; ++nq) {
        const int n = wn * 32 + nq * 16 + bx_r;
        boff[nq] = B_OFF + n * 32 + ((bx_h ^ ((n >> 2) & 1)) << 4);
    }

    // ---- cp.async chunk loader (A: 1024 x 16B -> 2/thread; B: 2048 -> 4) ---
#define LOAD_CHUNK(c)                                                               \
    do {                                                                            \
        const uint32_t st_ = sb + ((c) % NSTG) * STAGE;                             \
        const int kb_ = (c) * BK;                                                   \
        _Pragma("unroll")                                                           \
        for (int i = 0; i < 2; ++i) {                                               \
            const int u = tid + NTHR * i;        /* 1024 = 128m x 4ks x 2h */       \
            const int m = u >> 3, ks = (u >> 1) & 3, h = u & 1;                     \
            const size_t g = (size_t)(mBase + m) * Ee + kb_ + ks * 16 + h * 8;      \
            const uint32_t so = st_ + ks * 4096 + m * 32 + ((h ^ ((m >> 2) & 1)) << 4); \
            CPA16(so, g_ench + g);                                                  \
        }                                                                           \
        _Pragma("unroll")                                                           \
        for (int i = 0; i < 4; ++i) {                                               \
            const int u = tid + NTHR * i;        /* 2048 = 256n x 4ks x 2h */       \
            const int n = u >> 3, ks = (u >> 1) & 3, h = u & 1;                     \
            const size_t g = (size_t)(nBase + n) * Ee + kb_ + ks * 16 + h * 8;      \
            const uint32_t so = st_ + B_OFF + ks * 8192 + n * 32 + ((h ^ ((n >> 2) & 1)) << 4); \
            CPA16(so, g_weh + g);                                                   \
        }                                                                           \
    } while (0)

    float acc[4][4][4];
#pragma unroll
    for (int mf = 0; mf < 4; ++mf)
#pragma unroll
        for (int nf = 0; nf < 4; ++nf)
#pragma unroll
            for (int r = 0; r < 4; ++r) acc[mf][nf][r] = 0.0f;

    // prologue: 2 chunks in flight (3 buffers)
    LOAD_CHUNK(0); CPA_COMMIT();
    LOAD_CHUNK(1); CPA_COMMIT();

    for (int c = 0; c < NCH; ++c) {
        CPA_WAIT1();              // oldest group (chunk c) complete
        __syncthreads();          // publish; buffer (c+2)%3 (= c-1's) now free
        if (c + 2 < NCH) LOAD_CHUNK(c + 2);
        CPA_COMMIT();             // unconditional: fixed pending-group count
        const uint32_t st = sb + (c % NSTG) * STAGE;
#pragma unroll
        for (int ks = 0; ks < 4; ++ks) {
            const uint32_t ab = st + ks * 4096;
            const uint32_t bb = st + ks * 8192;
            uint32_t ah[4][4], bh[2][4];
#pragma unroll
            for (int mf = 0; mf < 4; ++mf)
                LDSM4(ah[mf], ab + aoff[mf]);
#pragma unroll
            for (int nq = 0; nq < 2; ++nq)
                LDSM4(bh[nq], bb + boff[nq]);
#pragma unroll
            for (int nq = 0; nq < 2; ++nq)
#pragma unroll
                for (int mf = 0; mf < 4; ++mf) {
                    MMA_F16(acc[mf][2 * nq + 0], ah[mf], bh[nq][0], bh[nq][1]);
                    MMA_F16(acc[mf][2 * nq + 1], ah[mf], bh[nq][2], bh[nq][3]);
                }
        }
    }
#undef LOAD_CHUNK

    // ---- fused epilogue: tanh(C + dec[b]) . v -> score partials ----------
    __syncthreads();
    float vt0[4], vt1[4];
#pragma unroll
    for (int nf = 0; nf < 4; ++nf) {
        const int n = nBase + wn * 32 + nf * 8 + 2 * (lane & 3);
        vt0[nf] = __ldg(&v[n]);
        vt1[nf] = __ldg(&v[n + 1]);
    }
    const float* decs = (const float*)(smem + DECOFF);
#pragma unroll
    for (int mf = 0; mf < 4; ++mf) {
#pragma unroll
        for (int rs = 0; rs < 2; ++rs) {
            const int mloc = wm * 64 + mf * 16 + rs * 8 + (lane >> 2);
            const int b = mloc & (Bb - 1);
            const int sIdx = (mBase + mloc) >> 5;
            float p = 0.0f;
#pragma unroll
            for (int nf = 0; nf < 4; ++nf) {
                const int nl = wn * 32 + nf * 8 + 2 * (lane & 3);
                const float c0 = acc[mf][nf][rs * 2 + 0] + decs[b * BN + nl];
                const float c1 = acc[mf][nf][rs * 2 + 1] + decs[b * BN + nl + 1];
                p += vt0[nf] * fast_tanh(c0) + vt1[nf] * fast_tanh(c1);
            }
            p += __shfl_xor_sync(0xffffffffu, p, 1);
            p += __shfl_xor_sync(0xffffffffu, p, 2);
            if ((lane & 3) == 0) atomicAdd(&g_scores[b * Ss + sIdx], p);
        }
    }
}

// ---------------------------------------------------------------------------
// K3: softmax over S per batch -> weights at d_out[32768 + b*S + s]
// ---------------------------------------------------------------------------
__global__ void k_softmax(float* __restrict__ out) {
    __shared__ float red[256];
    const int b = blockIdx.x;
    const int t = threadIdx.x;
    const float* sc = g_scores + b * Ss;
    float loc[8];
    float mx = -1e30f;
#pragma unroll
    for (int i = 0; i < 8; ++i) { loc[i] = sc[t + 256 * i]; mx = fmaxf(mx, loc[i]); }
    red[t] = mx; __syncthreads();
    for (int o = 128; o > 0; o >>= 1) { if (t < o) red[t] = fmaxf(red[t], red[t + o]); __syncthreads(); }
    mx = red[0]; __syncthreads();
    float sum = 0.0f;
#pragma unroll
    for (int i = 0; i < 8; ++i) { loc[i] = __expf(loc[i] - mx); sum += loc[i]; }
    red[t] = sum; __syncthreads();
    for (int o = 128; o > 0; o >>= 1) { if (t < o) red[t] += red[t + o]; __syncthreads(); }
    const float inv = 1.0f / red[0];
    float* w = out + Bb * Ee + b * Ss;
#pragma unroll
    for (int i = 0; i < 8; ++i) w[t + 256 * i] = loc[i] * inv;
}

// ---------------------------------------------------------------------------
// K4: context[b,e] = sum_s w[b,s] * enc_h[s,b,e]  (fp16 copy: half traffic)
// ---------------------------------------------------------------------------
__global__ void k_ctx(float* __restrict__ out) {
    const int b = blockIdx.y;
    const int e = blockIdx.x * 128 + threadIdx.x;
    const float* w = out + Bb * Ee + b * Ss;
    float a0 = 0.f, a1 = 0.f, a2 = 0.f, a3 = 0.f;
    for (int s = 0; s < Ss; s += 4) {
        a0 += w[s + 0] * __half2float(g_ench[((size_t)(s + 0) * Bb + b) * Ee + e]);
        a1 += w[s + 1] * __half2float(g_ench[((size_t)(s + 1) * Bb + b) * Ee + e]);
        a2 += w[s + 2] * __half2float(g_ench[((size_t)(s + 2) * Bb + b) * Ee + e]);
        a3 += w[s + 3] * __half2float(g_ench[((size_t)(s + 3) * Bb + b) * Ee + e]);
    }
    out[b * Ee + e] = (a0 + a1) + (a2 + a3);
}

// ---------------------------------------------------------------------------
// Launch: inputs: hidden, encoder_outputs, We, Wd, v
// Output: context[32,1024] then attention_weights[32,2048]
// ---------------------------------------------------------------------------
extern "C" void kernel_launch(void* const* d_in, const int* in_sizes, int n_in,
                              void* d_out, int out_size) {
    const float* hidden = (const float*)d_in[0];
    const float* enc    = (const float*)d_in[1];
    const float* We     = (const float*)d_in[2];
    const float* Wd     = (const float*)d_in[3];
    const float* v      = (const float*)d_in[4];
    float* out = (float*)d_out;

    cudaFuncSetAttribute(k_main, cudaFuncAttributeMaxDynamicSharedMemorySize, SMEMSZ);

    k_split_enc<<<8192, 256>>>((const float4*)enc);   // also zeroes g_scores
    k_split_we<<<512, 256>>>((const float4*)We);
    k_dec<<<Dd / 8, 256>>>(hidden, Wd);
    k_main<<<dim3(Dd / BN, Mm / BM), NTHR, SMEMSZ>>>(v);
    k_softmax<<<Bb, 256>>>(out);
    k_ctx<<<dim3(Ee / 128, Bb), 128>>>(out);
}